// round 1
// baseline (speedup 1.0000x reference)
#include <cuda_runtime.h>
#include <cstdint>
#include <cstddef>

#define VOCAB   50000
#define EMB     256
#define HID     512
#define NBATCH  256
#define T       512
#define NB      512            // both sequences stacked: batch rows 0..255 = seq1, 256..511 = seq2
#define KTOT    768            // EMB + HID
#define GB_H    32             // hid-group blocks
#define GB_B    4              // batch-group blocks
#define NBLOCKS (GB_H * GB_B)  // 128
#define HS      16             // hid units per block -> 64 gate rows
#define BS      128            // batch rows per block
#define KC      24             // K chunk staged per double-buffer slot
#define NCHUNK  (KTOT / KC)    // 32
#define THREADS 256

// SMEM layout (floats):
//   Ws   : 16*768*4 = 49152 floats (196608 B), swizzled weight tile [tj][k][q]
//   ins  : 2 * 128 * 28 = 7168 floats (28672 B), double-buffered input stage [buf][n][28]
//   toks : 128 ints (512 B)
#define WS_FLOATS   (HS * KTOT * 4)
#define INS_FLOATS  (2 * BS * 28)
#define SMEM_BYTES  ((WS_FLOATS + INS_FLOATS) * 4 + BS * 4)

__device__ float     g_h[2][NB * HID];   // double-buffered hidden state
__device__ unsigned  g_cnt;
__device__ unsigned  g_gen;

// ---------- small helpers ----------
__device__ __forceinline__ unsigned long long pack2(float lo, float hi) {
    unsigned long long r;
    asm("mov.b64 %0, {%1, %2};" : "=l"(r) : "f"(lo), "f"(hi));
    return r;
}
__device__ __forceinline__ float2 unpack2(unsigned long long v) {
    float lo, hi;
    asm("mov.b64 {%0, %1}, %2;" : "=f"(lo), "=f"(hi) : "l"(v));
    return make_float2(lo, hi);
}
__device__ __forceinline__ void ffma2(unsigned long long& acc,
                                      unsigned long long a, unsigned long long b) {
    asm("fma.rn.f32x2 %0, %1, %2, %0;" : "+l"(acc) : "l"(a), "l"(b));
}
__device__ __forceinline__ void cp16_ca(void* dst, const void* src) {
    unsigned d = (unsigned)__cvta_generic_to_shared(dst);
    asm volatile("cp.async.ca.shared.global [%0], [%1], 16;" :: "r"(d), "l"(src));
}
__device__ __forceinline__ void cp16_cg(void* dst, const void* src) {
    unsigned d = (unsigned)__cvta_generic_to_shared(dst);
    asm volatile("cp.async.cg.shared.global [%0], [%1], 16;" :: "r"(d), "l"(src));
}
__device__ __forceinline__ float sigf(float x) {
    return __fdividef(1.0f, 1.0f + __expf(-x));
}
__device__ __forceinline__ float tanhx(float x) {
    // tanh(x) = 2*sigmoid(2x) - 1  (accurate: __expf rel err ~2^-21)
    return __fmaf_rn(2.0f, sigf(2.0f * x), -1.0f);
}

// self-resetting grid barrier (all 128 CTAs guaranteed co-resident: 1 CTA/SM, 128 <= 148 SMs)
__device__ __forceinline__ void grid_sync() {
    __syncthreads();
    if (threadIdx.x == 0) {
        volatile unsigned* genp = &g_gen;
        unsigned g = *genp;
        __threadfence();
        if (atomicAdd(&g_cnt, 1u) == NBLOCKS - 1) {
            g_cnt = 0;
            __threadfence();
            *genp = g + 1;
        } else {
            while (*genp == g) { __nanosleep(40); }
        }
    }
    __syncthreads();
}

__global__ void __launch_bounds__(THREADS, 1)
lstm_twin_kernel(const int* __restrict__ in1, const int* __restrict__ in2,
                 const float* __restrict__ emb, const float* __restrict__ Wih,
                 const float* __restrict__ Whh, const float* __restrict__ bih,
                 const float* __restrict__ bhh, const float* __restrict__ Wfc,
                 const float* __restrict__ bfc, float* __restrict__ out)
{
    extern __shared__ float smem[];
    float* Ws  = smem;                       // swizzled weights
    float* ins = smem + WS_FLOATS;           // staging buffers
    int*   toks = (int*)(smem + WS_FLOATS + INS_FLOATS);

    const int tid = threadIdx.x;
    const int bid = blockIdx.x;
    const int hg  = bid & (GB_H - 1);        // 0..31
    const int bg  = bid >> 5;                // 0..3
    const int tb  = tid >> 4;                // 0..15 (batch sub-group)
    const int tj  = tid & 15;                // 0..15 (hid unit within tile)
    const int jglob = hg * HS + tj;
    const int nbase = bg * BS;
    const unsigned sw = (unsigned)(tj & 7);

    // ---- load weight tile into SMEM, layout Ws[tj][k][q] (16B cell per (tj,k)),
    //      swizzled: cell' = cell ^ (tj&7) to spread tj across 16B columns ----
    for (int r = 0; r < 4 * HS; r++) {
        int q   = r >> 4;
        int tjr = r & 15;
        int G   = q * HID + hg * HS + tjr;
        for (int k = tid; k < KTOT; k += THREADS) {
            float v = (k < EMB) ? Wih[G * EMB + k] : Whh[G * HID + (k - EMB)];
            unsigned cell = ((unsigned)(tjr * KTOT + k)) ^ ((unsigned)(tjr & 7));
            Ws[cell * 4 + q] = v;
        }
    }

    // bias (b_ih + b_hh), packed per gate-pair: (i,f) and (g,o)
    const unsigned long long bias01 =
        pack2(bih[0 * HID + jglob] + bhh[0 * HID + jglob],
              bih[1 * HID + jglob] + bhh[1 * HID + jglob]);
    const unsigned long long bias23 =
        pack2(bih[2 * HID + jglob] + bhh[2 * HID + jglob],
              bih[3 * HID + jglob] + bhh[3 * HID + jglob]);

    // zero h buffer 0 (read at t=0); buffer 1 is fully written at t=0
    {
        float* hz = &g_h[0][0];
        int base = (bid * THREADS + tid) * 8;
#pragma unroll
        for (int i = 0; i < 8; i++) hz[base + i] = 0.0f;
    }
    grid_sync();

    // staging assignment (per thread, 3 cp.async of 16B per chunk)
    int sn[3], sk[3];
#pragma unroll
    for (int s = 0; s < 3; s++) {
        int idx = tid + s * THREADS;   // 0..767 -> (n, kk4)
        sn[s] = idx / 6;
        sk[s] = idx % 6;
    }

    float c[8];
#pragma unroll
    for (int b = 0; b < 8; b++) c[b] = 0.0f;

    const ulonglong2* Ws2 = (const ulonglong2*)Ws;

#pragma unroll 1
    for (int t = 0; t < T; t++) {
        const float* hread  = &g_h[t & 1][0];
        float*       hwrite = &g_h[(t + 1) & 1][0];

        if (tid < BS) {
            int ng = nbase + tid;
            toks[tid] = (ng < NBATCH) ? in1[ng * T + t] : in2[(ng - NBATCH) * T + t];
        }
        __syncthreads();

        // stage chunk 0
#pragma unroll
        for (int s = 0; s < 3; s++) {
            int k4 = sk[s] * 4;
            float* dst = ins + sn[s] * 28 + sk[s] * 4;
            cp16_ca(dst, emb + (size_t)toks[sn[s]] * EMB + k4);   // chunk 0 is all-embedding
        }
        asm volatile("cp.async.commit_group;");

        unsigned long long acc[8][2];
#pragma unroll
        for (int b = 0; b < 8; b++) { acc[b][0] = bias01; acc[b][1] = bias23; }

#pragma unroll 1
        for (int cch = 0; cch < NCHUNK; cch++) {
            if (cch + 1 < NCHUNK) {
                const int k0n = (cch + 1) * KC;
                const int bsel = (cch + 1) & 1;
#pragma unroll
                for (int s = 0; s < 3; s++) {
                    int k4 = k0n + sk[s] * 4;
                    float* dst = ins + bsel * (BS * 28) + sn[s] * 28 + sk[s] * 4;
                    if (k4 < EMB) {
                        cp16_ca(dst, emb + (size_t)toks[sn[s]] * EMB + k4);
                    } else {
                        // .cg: bypass non-coherent L1 (h written by other SMs last step)
                        cp16_cg(dst, hread + (size_t)(nbase + sn[s]) * HID + (k4 - EMB));
                    }
                }
                asm volatile("cp.async.commit_group;");
                asm volatile("cp.async.wait_group 1;");
            } else {
                asm volatile("cp.async.wait_group 0;");
            }
            __syncthreads();

            const float4* xb = (const float4*)(ins + (cch & 1) * (BS * 28)) + tb * 8 * 7;
            const int k0 = cch * KC;
#pragma unroll
            for (int kk = 0; kk < KC / 4; kk++) {
                const unsigned cb = (unsigned)(tj * KTOT + k0 + kk * 4);
                ulonglong2 w0 = Ws2[(cb + 0) ^ sw];
                ulonglong2 w1 = Ws2[(cb + 1) ^ sw];
                ulonglong2 w2 = Ws2[(cb + 2) ^ sw];
                ulonglong2 w3 = Ws2[(cb + 3) ^ sw];
#pragma unroll
                for (int b = 0; b < 8; b++) {
                    float4 x = xb[b * 7 + kk];
                    unsigned long long d0 = pack2(x.x, x.x);
                    ffma2(acc[b][0], d0, w0.x); ffma2(acc[b][1], d0, w0.y);
                    unsigned long long d1 = pack2(x.y, x.y);
                    ffma2(acc[b][0], d1, w1.x); ffma2(acc[b][1], d1, w1.y);
                    unsigned long long d2 = pack2(x.z, x.z);
                    ffma2(acc[b][0], d2, w2.x); ffma2(acc[b][1], d2, w2.y);
                    unsigned long long d3 = pack2(x.w, x.w);
                    ffma2(acc[b][0], d3, w3.x); ffma2(acc[b][1], d3, w3.y);
                }
            }
            __syncthreads();
        }

        // pointwise LSTM cell update; acc[b][0] = (i,f) preact, acc[b][1] = (g,o)
#pragma unroll
        for (int b = 0; b < 8; b++) {
            float2 g01 = unpack2(acc[b][0]);
            float2 g23 = unpack2(acc[b][1]);
            float ig = sigf(g01.x);
            float fg = sigf(g01.y);
            float gg = tanhx(g23.x);
            float og = sigf(g23.y);
            c[b] = fg * c[b] + ig * gg;
            float hv = og * tanhx(c[b]);
            hwrite[(size_t)(nbase + tb * 8 + b) * HID + jglob] = hv;
        }

        grid_sync();
    }

    // ---- epilogue: h = h1*h2, logits = h @ Wfc^T + bfc, 2-way softmax ----
    // final h lives in g_h[T & 1] == g_h[0]
    if (bid == 0) {
        const int n = tid;  // 0..255
        const float* h1 = &g_h[0][(size_t)n * HID];
        const float* h2 = &g_h[0][(size_t)(n + NBATCH) * HID];
        float l0 = bfc[0], l1 = bfc[1];
#pragma unroll 4
        for (int j = 0; j < HID; j++) {
            float hp = __ldcg(&h1[j]) * __ldcg(&h2[j]);
            l0 = __fmaf_rn(hp, Wfc[j], l0);
            l1 = __fmaf_rn(hp, Wfc[HID + j], l1);
        }
        float m  = fmaxf(l0, l1);
        float e0 = __expf(l0 - m);
        float e1 = __expf(l1 - m);
        float s  = __fdividef(1.0f, e0 + e1);
        out[n * 2 + 0] = e0 * s;
        out[n * 2 + 1] = e1 * s;
    }
}

extern "C" void kernel_launch(void* const* d_in, const int* in_sizes, int n_in,
                              void* d_out, int out_size)
{
    (void)in_sizes; (void)n_in; (void)out_size;
    const int*   in1 = (const int*)d_in[0];
    const int*   in2 = (const int*)d_in[1];
    const float* emb = (const float*)d_in[2];
    const float* Wih = (const float*)d_in[3];
    const float* Whh = (const float*)d_in[4];
    const float* bih = (const float*)d_in[5];
    const float* bhh = (const float*)d_in[6];
    const float* Wfc = (const float*)d_in[7];
    const float* bfc = (const float*)d_in[8];
    float* out = (float*)d_out;

    cudaFuncSetAttribute(lstm_twin_kernel,
                         cudaFuncAttributeMaxDynamicSharedMemorySize, SMEM_BYTES);
    lstm_twin_kernel<<<NBLOCKS, THREADS, SMEM_BYTES>>>(
        in1, in2, emb, Wih, Whh, bih, bhh, Wfc, bfc, out);
}

// round 2
// speedup vs baseline: 1.0529x; 1.0529x over previous
#include <cuda_runtime.h>
#include <cstdint>
#include <cstddef>

#define VOCAB   50000
#define EMB     256
#define HID     512
#define NBATCH  256
#define T       512
#define NB      512            // both sequences stacked
#define KTOT    768            // EMB + HID
#define GB_H    32
#define GB_B    4
#define NBLOCKS (GB_H * GB_B)  // 128
#define HS      16             // hid units per block -> 64 gate rows
#define BS      128            // batch rows per block
#define KC      32             // K chunk per double-buffer slot
#define NCHUNK  (KTOT / KC)    // 24
#define THREADS 512

// SMEM (floats): Ws 49152 (192KB) + ins 2*128*32=8192 (32KB) + toks 128 ints
#define WS_FLOATS   (HS * KTOT * 4)
#define INS_FLOATS  (2 * BS * KC)
#define SMEM_BYTES  ((WS_FLOATS + INS_FLOATS) * 4 + BS * 4)

__device__ float     g_h[2][NB * HID];
__device__ unsigned  g_cnt;
__device__ unsigned  g_gen;

__device__ __forceinline__ unsigned long long pack2(float lo, float hi) {
    unsigned long long r;
    asm("mov.b64 %0, {%1, %2};" : "=l"(r) : "f"(lo), "f"(hi));
    return r;
}
__device__ __forceinline__ float2 unpack2(unsigned long long v) {
    float lo, hi;
    asm("mov.b64 {%0, %1}, %2;" : "=f"(lo), "=f"(hi) : "l"(v));
    return make_float2(lo, hi);
}
__device__ __forceinline__ void ffma2(unsigned long long& acc,
                                      unsigned long long a, unsigned long long b) {
    asm("fma.rn.f32x2 %0, %1, %2, %0;" : "+l"(acc) : "l"(a), "l"(b));
}
__device__ __forceinline__ void cp16_ca(void* dst, const void* src) {
    unsigned d = (unsigned)__cvta_generic_to_shared(dst);
    asm volatile("cp.async.ca.shared.global [%0], [%1], 16;" :: "r"(d), "l"(src));
}
__device__ __forceinline__ void cp16_cg(void* dst, const void* src) {
    unsigned d = (unsigned)__cvta_generic_to_shared(dst);
    asm volatile("cp.async.cg.shared.global [%0], [%1], 16;" :: "r"(d), "l"(src));
}
__device__ __forceinline__ float sigf(float x) {
    return __fdividef(1.0f, 1.0f + __expf(-x));
}
__device__ __forceinline__ float tanhx(float x) {
    return __fmaf_rn(2.0f, sigf(2.0f * x), -1.0f);
}

__device__ __forceinline__ void grid_sync() {
    __syncthreads();
    if (threadIdx.x == 0) {
        volatile unsigned* genp = &g_gen;
        unsigned g = *genp;
        __threadfence();
        if (atomicAdd(&g_cnt, 1u) == NBLOCKS - 1) {
            g_cnt = 0;
            __threadfence();
            *genp = g + 1;
        } else {
            while (*genp == g) { __nanosleep(40); }
        }
    }
    __syncthreads();
}

__global__ void __launch_bounds__(THREADS, 1)
lstm_twin_kernel(const int* __restrict__ in1, const int* __restrict__ in2,
                 const float* __restrict__ emb, const float* __restrict__ Wih,
                 const float* __restrict__ Whh, const float* __restrict__ bih,
                 const float* __restrict__ bhh, const float* __restrict__ Wfc,
                 const float* __restrict__ bfc, float* __restrict__ out)
{
    extern __shared__ float smem[];
    float* Ws  = smem;
    float* ins = smem + WS_FLOATS;
    int*   toks = (int*)(smem + WS_FLOATS + INS_FLOATS);

    const int tid = threadIdx.x;
    const int bid = blockIdx.x;
    const int hg  = bid & (GB_H - 1);
    const int bg  = bid >> 5;
    const int tb  = tid >> 4;               // 0..31, each owns 4 batch rows
    const int tj  = tid & 15;               // hid unit within tile
    const int jglob = hg * HS + tj;
    const int nbase = bg * BS;
    const unsigned sw = (unsigned)(tj & 7);

    // weight tile -> SMEM, Ws[tj][k][q] 16B cells, swizzled by tj&7
    for (int r = 0; r < 4 * HS; r++) {
        int q   = r >> 4;
        int tjr = r & 15;
        int G   = q * HID + hg * HS + tjr;
        for (int k = tid; k < KTOT; k += THREADS) {
            float v = (k < EMB) ? Wih[G * EMB + k] : Whh[G * HID + (k - EMB)];
            unsigned cell = ((unsigned)(tjr * KTOT + k)) ^ ((unsigned)(tjr & 7));
            Ws[cell * 4 + q] = v;
        }
    }

    const unsigned long long bias01 =
        pack2(bih[0 * HID + jglob] + bhh[0 * HID + jglob],
              bih[1 * HID + jglob] + bhh[1 * HID + jglob]);
    const unsigned long long bias23 =
        pack2(bih[2 * HID + jglob] + bhh[2 * HID + jglob],
              bih[3 * HID + jglob] + bhh[3 * HID + jglob]);

    // zero h buffer 0
    {
        float* hz = &g_h[0][0];
        int base = (bid * THREADS + tid) * 4;
#pragma unroll
        for (int i = 0; i < 4; i++) hz[base + i] = 0.0f;
    }
    grid_sync();

    // staging: 1024 16B-cells per chunk, 2 per thread
    int sn[2], sk[2];
#pragma unroll
    for (int s = 0; s < 2; s++) {
        int idx = tid + s * THREADS;  // 0..1023
        sn[s] = idx >> 3;             // 0..127
        sk[s] = idx & 7;              // 0..7
    }

    float c[4];
#pragma unroll
    for (int b = 0; b < 4; b++) c[b] = 0.0f;

    const ulonglong2* Ws2 = (const ulonglong2*)Ws;

#pragma unroll 1
    for (int t = 0; t < T; t++) {
        const float* hread  = &g_h[t & 1][0];
        float*       hwrite = &g_h[(t + 1) & 1][0];

        if (tid < BS) {
            int ng = nbase + tid;
            toks[tid] = (ng < NBATCH) ? in1[ng * T + t] : in2[(ng - NBATCH) * T + t];
        }
        __syncthreads();

        // stage chunk 0 (all-embedding: k < 32 < EMB)
#pragma unroll
        for (int s = 0; s < 2; s++) {
            float* dst = ins + sn[s] * KC + sk[s] * 4;
            cp16_ca(dst, emb + (size_t)toks[sn[s]] * EMB + sk[s] * 4);
        }
        asm volatile("cp.async.commit_group;");

        unsigned long long acc[4][2];
#pragma unroll
        for (int b = 0; b < 4; b++) { acc[b][0] = bias01; acc[b][1] = bias23; }

#pragma unroll 1
        for (int cch = 0; cch < NCHUNK; cch++) {
            if (cch + 1 < NCHUNK) {
                const int k0n  = (cch + 1) * KC;
                const int bsel = (cch + 1) & 1;
#pragma unroll
                for (int s = 0; s < 2; s++) {
                    int k4 = k0n + sk[s] * 4;
                    float* dst = ins + bsel * (BS * KC) + sn[s] * KC + sk[s] * 4;
                    if (k4 < EMB) {
                        cp16_ca(dst, emb + (size_t)toks[sn[s]] * EMB + k4);
                    } else {
                        cp16_cg(dst, hread + (size_t)(nbase + sn[s]) * HID + (k4 - EMB));
                    }
                }
                asm volatile("cp.async.commit_group;");
                asm volatile("cp.async.wait_group 1;");
            } else {
                asm volatile("cp.async.wait_group 0;");
            }
            __syncthreads();

            const float4* xb = (const float4*)(ins + (cch & 1) * (BS * KC)) + tb * 4 * (KC / 4);
            const int k0 = cch * KC;
#pragma unroll
            for (int kk = 0; kk < KC / 4; kk++) {
                const unsigned cb = (unsigned)(tj * KTOT + k0 + kk * 4);
                ulonglong2 w0 = Ws2[(cb + 0) ^ sw];
                ulonglong2 w1 = Ws2[(cb + 1) ^ sw];
                ulonglong2 w2 = Ws2[(cb + 2) ^ sw];
                ulonglong2 w3 = Ws2[(cb + 3) ^ sw];
#pragma unroll
                for (int b = 0; b < 4; b++) {
                    float4 x = xb[b * (KC / 4) + kk];
                    unsigned long long d0 = pack2(x.x, x.x);
                    ffma2(acc[b][0], d0, w0.x); ffma2(acc[b][1], d0, w0.y);
                    unsigned long long d1 = pack2(x.y, x.y);
                    ffma2(acc[b][0], d1, w1.x); ffma2(acc[b][1], d1, w1.y);
                    unsigned long long d2 = pack2(x.z, x.z);
                    ffma2(acc[b][0], d2, w2.x); ffma2(acc[b][1], d2, w2.y);
                    unsigned long long d3 = pack2(x.w, x.w);
                    ffma2(acc[b][0], d3, w3.x); ffma2(acc[b][1], d3, w3.y);
                }
            }
            __syncthreads();
        }

        // pointwise LSTM cell
#pragma unroll
        for (int b = 0; b < 4; b++) {
            float2 g01 = unpack2(acc[b][0]);
            float2 g23 = unpack2(acc[b][1]);
            float ig = sigf(g01.x);
            float fg = sigf(g01.y);
            float gg = tanhx(g23.x);
            float og = sigf(g23.y);
            c[b] = fg * c[b] + ig * gg;
            float hv = og * tanhx(c[b]);
            hwrite[(size_t)(nbase + tb * 4 + b) * HID + jglob] = hv;
        }

        grid_sync();
    }

    // epilogue
    if (bid == 0 && tid < NBATCH) {
        const int n = tid;
        const float* h1 = &g_h[0][(size_t)n * HID];
        const float* h2 = &g_h[0][(size_t)(n + NBATCH) * HID];
        float l0 = bfc[0], l1 = bfc[1];
#pragma unroll 4
        for (int j = 0; j < HID; j++) {
            float hp = __ldcg(&h1[j]) * __ldcg(&h2[j]);
            l0 = __fmaf_rn(hp, Wfc[j], l0);
            l1 = __fmaf_rn(hp, Wfc[HID + j], l1);
        }
        float m  = fmaxf(l0, l1);
        float e0 = __expf(l0 - m);
        float e1 = __expf(l1 - m);
        float s  = __fdividef(1.0f, e0 + e1);
        out[n * 2 + 0] = e0 * s;
        out[n * 2 + 1] = e1 * s;
    }
}

extern "C" void kernel_launch(void* const* d_in, const int* in_sizes, int n_in,
                              void* d_out, int out_size)
{
    (void)in_sizes; (void)n_in; (void)out_size;
    const int*   in1 = (const int*)d_in[0];
    const int*   in2 = (const int*)d_in[1];
    const float* emb = (const float*)d_in[2];
    const float* Wih = (const float*)d_in[3];
    const float* Whh = (const float*)d_in[4];
    const float* bih = (const float*)d_in[5];
    const float* bhh = (const float*)d_in[6];
    const float* Wfc = (const float*)d_in[7];
    const float* bfc = (const float*)d_in[8];
    float* out = (float*)d_out;

    cudaFuncSetAttribute(lstm_twin_kernel,
                         cudaFuncAttributeMaxDynamicSharedMemorySize, SMEM_BYTES);
    lstm_twin_kernel<<<NBLOCKS, THREADS, SMEM_BYTES>>>(
        in1, in2, emb, Wih, Whh, bih, bhh, Wfc, bfc, out);
}

// round 3
// speedup vs baseline: 1.1274x; 1.0708x over previous
#include <cuda_runtime.h>
#include <cstdint>
#include <cstddef>

#define VOCAB   50000
#define EMB     256
#define HID     512
#define NBATCH  256
#define T       512
#define NB      512
#define KTOT    768            // EMB + HID
#define GB_H    32
#define GB_B    4
#define NBLOCKS (GB_H * GB_B)  // 128
#define HS      16             // hid units per block -> 64 gate rows
#define BS      128            // batch rows per block
#define KC      32             // K chunk per buffer slot
#define NCHUNK  (KTOT / KC)    // 24
#define THREADS 512
#define NWARP   16
#define BUFW    (8 * KC)       // floats per (warp, buffer) slice

// SMEM: weights 49152 floats (192KB) + staging 16*2*256 floats (32KB) = 229376 B
#define WS_FLOATS   (HS * KTOT * 4)
#define INS_FLOATS  (NWARP * 2 * BUFW)
#define SMEM_BYTES  ((WS_FLOATS + INS_FLOATS) * 4)

__device__ float     g_h[2][NB * HID];
__device__ unsigned  g_cnt;
__device__ unsigned  g_gen;

__device__ __forceinline__ unsigned long long pack2(float lo, float hi) {
    unsigned long long r;
    asm("mov.b64 %0, {%1, %2};" : "=l"(r) : "f"(lo), "f"(hi));
    return r;
}
__device__ __forceinline__ float2 unpack2(unsigned long long v) {
    float lo, hi;
    asm("mov.b64 {%0, %1}, %2;" : "=f"(lo), "=f"(hi) : "l"(v));
    return make_float2(lo, hi);
}
__device__ __forceinline__ void ffma2(unsigned long long& acc,
                                      unsigned long long a, unsigned long long b) {
    asm("fma.rn.f32x2 %0, %1, %2, %0;" : "+l"(acc) : "l"(a), "l"(b));
}
__device__ __forceinline__ void cp16_ca(void* dst, const void* src) {
    unsigned d = (unsigned)__cvta_generic_to_shared(dst);
    asm volatile("cp.async.ca.shared.global [%0], [%1], 16;" :: "r"(d), "l"(src));
}
__device__ __forceinline__ void cp16_cg(void* dst, const void* src) {
    unsigned d = (unsigned)__cvta_generic_to_shared(dst);
    asm volatile("cp.async.cg.shared.global [%0], [%1], 16;" :: "r"(d), "l"(src));
}
__device__ __forceinline__ float sigf(float x) {
    return __fdividef(1.0f, 1.0f + __expf(-x));
}
__device__ __forceinline__ float tanhx(float x) {
    return __fmaf_rn(2.0f, sigf(2.0f * x), -1.0f);
}

__device__ __forceinline__ void grid_sync() {
    __syncthreads();
    if (threadIdx.x == 0) {
        volatile unsigned* genp = &g_gen;
        unsigned g = *genp;
        __threadfence();
        if (atomicAdd(&g_cnt, 1u) == NBLOCKS - 1) {
            g_cnt = 0;
            __threadfence();
            *genp = g + 1;
        } else {
            while (*genp == g) { __nanosleep(40); }
        }
    }
    __syncthreads();
}

__global__ void __launch_bounds__(THREADS, 1)
lstm_twin_kernel(const int* __restrict__ in1, const int* __restrict__ in2,
                 const float* __restrict__ emb, const float* __restrict__ Wih,
                 const float* __restrict__ Whh, const float* __restrict__ bih,
                 const float* __restrict__ bhh, const float* __restrict__ Wfc,
                 const float* __restrict__ bfc, float* __restrict__ out)
{
    extern __shared__ float smem[];
    float* Ws  = smem;
    float* ins = smem + WS_FLOATS;

    const int tid = threadIdx.x;
    const int bid = blockIdx.x;
    const int hg  = bid & (GB_H - 1);
    const int bg  = bid >> 5;
    const int w   = tid >> 5;            // warp 0..15
    const int lid = tid & 31;
    const int tbw = (tid >> 4) & 1;      // batch half within warp
    const int tj  = tid & 15;            // hid unit within tile
    const int jglob = hg * HS + tj;
    const int nbase = bg * BS;
    const int nb0   = nbase + 8 * w;     // this warp's first batch row
    const unsigned sw = (unsigned)(tj & 7);
    const int warpbase = w * 2 * BUFW;   // float offset of this warp's staging

    // ---- weight tile -> SMEM, Ws[tj][k][q] 16B cells, swizzled by tj&7 ----
    for (int r = 0; r < 4 * HS; r++) {
        int q   = r >> 4;
        int tjr = r & 15;
        int G   = q * HID + hg * HS + tjr;
        for (int k = tid; k < KTOT; k += THREADS) {
            float v = (k < EMB) ? Wih[G * EMB + k] : Whh[G * HID + (k - EMB)];
            unsigned cell = ((unsigned)(tjr * KTOT + k)) ^ ((unsigned)(tjr & 7));
            Ws[cell * 4 + q] = v;
        }
    }

    const unsigned long long bias01 =
        pack2(bih[0 * HID + jglob] + bhh[0 * HID + jglob],
              bih[1 * HID + jglob] + bhh[1 * HID + jglob]);
    const unsigned long long bias23 =
        pack2(bih[2 * HID + jglob] + bhh[2 * HID + jglob],
              bih[3 * HID + jglob] + bhh[3 * HID + jglob]);

    // zero h buffer 0
    {
        float* hz = &g_h[0][0];
        int base = (bid * THREADS + tid) * 4;
#pragma unroll
        for (int i = 0; i < 4; i++) hz[base + i] = 0.0f;
    }
    grid_sync();

    // ---- warp-private staging assignment: lane stages 2 cells (16B each) ----
    const int kc  = lid & 7;             // cell column 0..7
    const int kc4 = kc * 4;              // float offset within chunk
    const int r0  = lid >> 3;            // 0..3
    const int r1  = r0 + 4;              // 4..7
    const int d0  = r0 * 32 + ((kc ^ r0) << 2);   // swizzled float offsets
    const int d1  = r1 * 32 + ((kc ^ r1) << 2);
    const int hrow0 = (nb0 + r0) * HID;
    const int hrow1 = (nb0 + r1) * HID;

    // token pointers (CTA uniform input array: bg<2 -> in1, else in2)
    const int* tokarr = (bg < 2) ? in1 : in2;
    const int  rowb   = (nbase & (NBATCH - 1)) + 8 * w;
    const int* tp0 = tokarr + (size_t)(rowb + r0) * T;
    const int* tp1 = tokarr + (size_t)(rowb + r1) * T;

    int cur0 = __ldg(tp0);      // tokens for t=0
    int cur1 = __ldg(tp1);

    float c[4];
#pragma unroll
    for (int b = 0; b < 4; b++) c[b] = 0.0f;

    const ulonglong2* Ws2 = (const ulonglong2*)Ws;

#pragma unroll 1
    for (int t = 0; t < T; t++) {
        const float* hread  = &g_h[t & 1][0];
        float*       hwrite = &g_h[(t + 1) & 1][0];

        const float* esrc0 = emb + (size_t)cur0 * EMB + kc4;
        const float* esrc1 = emb + (size_t)cur1 * EMB + kc4;

        // stage chunks 0 and 1 (both all-embedding)
        {
            float* db0 = ins + warpbase;           // buf 0
            cp16_ca(db0 + d0, esrc0 + 0);
            cp16_ca(db0 + d1, esrc1 + 0);
            asm volatile("cp.async.commit_group;");
            float* db1 = ins + warpbase + BUFW;    // buf 1
            cp16_ca(db1 + d0, esrc0 + KC);
            cp16_ca(db1 + d1, esrc1 + KC);
            asm volatile("cp.async.commit_group;");
        }

        // prefetch next step's tokens (independent of this step)
        const int tn = (t + 1 < T) ? t + 1 : t;
        int nxt0 = __ldg(tp0 + tn);
        int nxt1 = __ldg(tp1 + tn);

        unsigned long long acc[4][2];
#pragma unroll
        for (int b = 0; b < 4; b++) { acc[b][0] = bias01; acc[b][1] = bias23; }

#pragma unroll 1
        for (int cch = 0; cch < NCHUNK; cch++) {
            if (cch == NCHUNK - 1) {
                asm volatile("cp.async.wait_group 0;");
            } else {
                asm volatile("cp.async.wait_group 1;");
            }

            const float* xb = ins + warpbase + (cch & 1) * BUFW;
            const int k0 = cch * KC;
#pragma unroll
            for (int kk = 0; kk < KC / 4; kk++) {
                const unsigned cb = (unsigned)(tj * KTOT + k0 + kk * 4);
                ulonglong2 w0 = Ws2[(cb + 0) ^ sw];
                ulonglong2 w1 = Ws2[(cb + 1) ^ sw];
                ulonglong2 w2 = Ws2[(cb + 2) ^ sw];
                ulonglong2 w3 = Ws2[(cb + 3) ^ sw];
#pragma unroll
                for (int b = 0; b < 4; b++) {
                    const int r = tbw * 4 + b;
                    float4 x = *(const float4*)(xb + r * 32 + ((kk ^ r) << 2));
                    unsigned long long dd0 = pack2(x.x, x.x);
                    ffma2(acc[b][0], dd0, w0.x); ffma2(acc[b][1], dd0, w0.y);
                    unsigned long long dd1 = pack2(x.y, x.y);
                    ffma2(acc[b][0], dd1, w1.x); ffma2(acc[b][1], dd1, w1.y);
                    unsigned long long dd2 = pack2(x.z, x.z);
                    ffma2(acc[b][0], dd2, w2.x); ffma2(acc[b][1], dd2, w2.y);
                    unsigned long long dd3 = pack2(x.w, x.w);
                    ffma2(acc[b][0], dd3, w3.x); ffma2(acc[b][1], dd3, w3.y);
                }
            }

            // stage chunk cch+2 into the buffer we just finished reading
            if (cch + 2 < NCHUNK) {
                const int k0n = (cch + 2) * KC;
                float* dst = ins + warpbase + (cch & 1) * BUFW;
                if (k0n < EMB) {
                    cp16_ca(dst + d0, esrc0 + k0n);
                    cp16_ca(dst + d1, esrc1 + k0n);
                } else {
                    const int ho = k0n - EMB + kc4;
                    cp16_cg(dst + d0, hread + hrow0 + ho);
                    cp16_cg(dst + d1, hread + hrow1 + ho);
                }
                asm volatile("cp.async.commit_group;");
            }
        }

        // pointwise LSTM cell
#pragma unroll
        for (int b = 0; b < 4; b++) {
            float2 g01 = unpack2(acc[b][0]);
            float2 g23 = unpack2(acc[b][1]);
            float ig = sigf(g01.x);
            float fg = sigf(g01.y);
            float gg = tanhx(g23.x);
            float og = sigf(g23.y);
            c[b] = fg * c[b] + ig * gg;
            float hv = og * tanhx(c[b]);
            hwrite[(size_t)(nb0 + tbw * 4 + b) * HID + jglob] = hv;
        }

        cur0 = nxt0;
        cur1 = nxt1;
        grid_sync();
    }

    // epilogue: h = h1*h2 -> FC(2) -> softmax
    if (bid == 0 && tid < NBATCH) {
        const int n = tid;
        const float* h1 = &g_h[0][(size_t)n * HID];
        const float* h2 = &g_h[0][(size_t)(n + NBATCH) * HID];
        float l0 = bfc[0], l1 = bfc[1];
#pragma unroll 4
        for (int j = 0; j < HID; j++) {
            float hp = __ldcg(&h1[j]) * __ldcg(&h2[j]);
            l0 = __fmaf_rn(hp, Wfc[j], l0);
            l1 = __fmaf_rn(hp, Wfc[HID + j], l1);
        }
        float m  = fmaxf(l0, l1);
        float e0 = __expf(l0 - m);
        float e1 = __expf(l1 - m);
        float s  = __fdividef(1.0f, e0 + e1);
        out[n * 2 + 0] = e0 * s;
        out[n * 2 + 1] = e1 * s;
    }
}

extern "C" void kernel_launch(void* const* d_in, const int* in_sizes, int n_in,
                              void* d_out, int out_size)
{
    (void)in_sizes; (void)n_in; (void)out_size;
    const int*   in1 = (const int*)d_in[0];
    const int*   in2 = (const int*)d_in[1];
    const float* emb = (const float*)d_in[2];
    const float* Wih = (const float*)d_in[3];
    const float* Whh = (const float*)d_in[4];
    const float* bih = (const float*)d_in[5];
    const float* bhh = (const float*)d_in[6];
    const float* Wfc = (const float*)d_in[7];
    const float* bfc = (const float*)d_in[8];
    float* out = (float*)d_out;

    cudaFuncSetAttribute(lstm_twin_kernel,
                         cudaFuncAttributeMaxDynamicSharedMemorySize, SMEM_BYTES);
    lstm_twin_kernel<<<NBLOCKS, THREADS, SMEM_BYTES>>>(
        in1, in2, emb, Wih, Whh, bih, bhh, Wfc, bfc, out);
}

// round 4
// speedup vs baseline: 1.1307x; 1.0030x over previous
#include <cuda_runtime.h>
#include <cstdint>
#include <cstddef>

#define VOCAB   50000
#define EMB     256
#define HID     512
#define NBATCH  256
#define T       512
#define NB      512
#define KTOT    768            // EMB + HID
#define GB_H    32
#define GB_B    4
#define NBLOCKS (GB_H * GB_B)  // 128
#define HS      16             // hid units per block -> 64 gate rows
#define BS      128            // batch rows per block
#define KC      32             // K chunk per buffer slot
#define NCHUNK  (KTOT / KC)    // 24
#define THREADS 512
#define NWARP   16
#define BUFW    (8 * KC)       // floats per (warp, buffer) slice

// SMEM: weights 49152 floats (192KB) + staging 16*2*256 floats (32KB) = 229376 B
#define WS_FLOATS   (HS * KTOT * 4)
#define INS_FLOATS  (NWARP * 2 * BUFW)
#define SMEM_BYTES  ((WS_FLOATS + INS_FLOATS) * 4)

__device__ float     g_h[2][NB * HID];
__device__ unsigned  g_cnt;
__device__ unsigned  g_gen;

__device__ __forceinline__ unsigned long long pack2(float lo, float hi) {
    unsigned long long r;
    asm("mov.b64 %0, {%1, %2};" : "=l"(r) : "f"(lo), "f"(hi));
    return r;
}
__device__ __forceinline__ float2 unpack2(unsigned long long v) {
    float lo, hi;
    asm("mov.b64 {%0, %1}, %2;" : "=f"(lo), "=f"(hi) : "l"(v));
    return make_float2(lo, hi);
}
__device__ __forceinline__ void ffma2(unsigned long long& acc,
                                      unsigned long long a, unsigned long long b) {
    asm("fma.rn.f32x2 %0, %1, %2, %0;" : "+l"(acc) : "l"(a), "l"(b));
}
__device__ __forceinline__ void cp16_ca(void* dst, const void* src) {
    unsigned d = (unsigned)__cvta_generic_to_shared(dst);
    asm volatile("cp.async.ca.shared.global [%0], [%1], 16;" :: "r"(d), "l"(src));
}
__device__ __forceinline__ void cp16_cg(void* dst, const void* src) {
    unsigned d = (unsigned)__cvta_generic_to_shared(dst);
    asm volatile("cp.async.cg.shared.global [%0], [%1], 16;" :: "r"(d), "l"(src));
}
__device__ __forceinline__ float sigf(float x) {
    return __fdividef(1.0f, 1.0f + __expf(-x));
}
__device__ __forceinline__ float tanhx(float x) {
    return __fmaf_rn(2.0f, sigf(2.0f * x), -1.0f);
}

__device__ __forceinline__ void grid_sync() {
    __syncthreads();
    if (threadIdx.x == 0) {
        volatile unsigned* genp = &g_gen;
        unsigned g = *genp;
        __threadfence();
        if (atomicAdd(&g_cnt, 1u) == NBLOCKS - 1) {
            g_cnt = 0;
            __threadfence();
            *genp = g + 1;
        } else {
            while (*genp == g) { __nanosleep(40); }
        }
    }
    __syncthreads();
}

__global__ void __launch_bounds__(THREADS, 1)
lstm_twin_kernel(const int* __restrict__ in1, const int* __restrict__ in2,
                 const float* __restrict__ emb, const float* __restrict__ Wih,
                 const float* __restrict__ Whh, const float* __restrict__ bih,
                 const float* __restrict__ bhh, const float* __restrict__ Wfc,
                 const float* __restrict__ bfc, float* __restrict__ out)
{
    extern __shared__ float smem[];
    float* Ws  = smem;
    float* ins = smem + WS_FLOATS;

    const int tid = threadIdx.x;
    const int bid = blockIdx.x;
    const int hg  = bid & (GB_H - 1);
    const int bg  = bid >> 5;
    const int w   = tid >> 5;            // warp 0..15
    const int lid = tid & 31;
    const int tbw = (tid >> 4) & 1;      // batch half within warp
    const int tj  = tid & 15;            // hid unit within tile
    const int jglob = hg * HS + tj;
    const int nbase = bg * BS;
    const int nb0   = nbase + 8 * w;     // this warp's first batch row
    const unsigned sw = (unsigned)(tj & 7);
    const int warpbase = w * 2 * BUFW;   // float offset of this warp's staging

    // ---- weight tile -> SMEM, Ws[tj][k][q] 16B cells, swizzled by tj&7 ----
    for (int r = 0; r < 4 * HS; r++) {
        int q   = r >> 4;
        int tjr = r & 15;
        int G   = q * HID + hg * HS + tjr;
        for (int k = tid; k < KTOT; k += THREADS) {
            float v = (k < EMB) ? Wih[G * EMB + k] : Whh[G * HID + (k - EMB)];
            unsigned cell = ((unsigned)(tjr * KTOT + k)) ^ ((unsigned)(tjr & 7));
            Ws[cell * 4 + q] = v;
        }
    }

    const unsigned long long bias01 =
        pack2(bih[0 * HID + jglob] + bhh[0 * HID + jglob],
              bih[1 * HID + jglob] + bhh[1 * HID + jglob]);
    const unsigned long long bias23 =
        pack2(bih[2 * HID + jglob] + bhh[2 * HID + jglob],
              bih[3 * HID + jglob] + bhh[3 * HID + jglob]);

    // zero h buffer 0
    {
        float* hz = &g_h[0][0];
        int base = (bid * THREADS + tid) * 4;
#pragma unroll
        for (int i = 0; i < 4; i++) hz[base + i] = 0.0f;
    }
    grid_sync();

    // ---- warp-private staging assignment: lane stages 2 cells (16B each) ----
    const int kc  = lid & 7;             // cell column 0..7
    const int kc4 = kc * 4;              // float offset within chunk
    const int r0  = lid >> 3;            // 0..3
    const int r1  = r0 + 4;              // 4..7
    const int d0  = r0 * 32 + ((kc ^ r0) << 2);   // swizzled float offsets
    const int d1  = r1 * 32 + ((kc ^ r1) << 2);
    const int hrow0 = (nb0 + r0) * HID;
    const int hrow1 = (nb0 + r1) * HID;

    // token pointers (CTA uniform input array: bg<2 -> in1, else in2)
    const int* tokarr = (bg < 2) ? in1 : in2;
    const int  rowb   = (nbase & (NBATCH - 1)) + 8 * w;
    const int* tp0 = tokarr + (size_t)(rowb + r0) * T;
    const int* tp1 = tokarr + (size_t)(rowb + r1) * T;

    int cur0 = __ldg(tp0);      // tokens for t=0
    int cur1 = __ldg(tp1);

    float c[4];
#pragma unroll
    for (int b = 0; b < 4; b++) c[b] = 0.0f;

    const ulonglong2* Ws2 = (const ulonglong2*)Ws;

#pragma unroll 1
    for (int t = 0; t < T; t++) {
        const float* hread  = &g_h[t & 1][0];
        float*       hwrite = &g_h[(t + 1) & 1][0];

        const float* esrc0 = emb + (size_t)cur0 * EMB + kc4;
        const float* esrc1 = emb + (size_t)cur1 * EMB + kc4;

        // stage chunks 0 and 1 (both all-embedding)
        {
            float* db0 = ins + warpbase;           // buf 0
            cp16_ca(db0 + d0, esrc0 + 0);
            cp16_ca(db0 + d1, esrc1 + 0);
            asm volatile("cp.async.commit_group;");
            float* db1 = ins + warpbase + BUFW;    // buf 1
            cp16_ca(db1 + d0, esrc0 + KC);
            cp16_ca(db1 + d1, esrc1 + KC);
            asm volatile("cp.async.commit_group;");
        }

        // prefetch next step's tokens (independent of this step)
        const int tn = (t + 1 < T) ? t + 1 : t;
        int nxt0 = __ldg(tp0 + tn);
        int nxt1 = __ldg(tp1 + tn);

        unsigned long long acc[4][2];
#pragma unroll
        for (int b = 0; b < 4; b++) { acc[b][0] = bias01; acc[b][1] = bias23; }

#pragma unroll 1
        for (int cch = 0; cch < NCHUNK; cch++) {
            if (cch == NCHUNK - 1) {
                asm volatile("cp.async.wait_group 0;");
            } else {
                asm volatile("cp.async.wait_group 1;");
            }

            const float* xb = ins + warpbase + (cch & 1) * BUFW;
            const int k0 = cch * KC;
#pragma unroll
            for (int kk = 0; kk < KC / 4; kk++) {
                const unsigned cb = (unsigned)(tj * KTOT + k0 + kk * 4);
                ulonglong2 w0 = Ws2[(cb + 0) ^ sw];
                ulonglong2 w1 = Ws2[(cb + 1) ^ sw];
                ulonglong2 w2 = Ws2[(cb + 2) ^ sw];
                ulonglong2 w3 = Ws2[(cb + 3) ^ sw];
#pragma unroll
                for (int b = 0; b < 4; b++) {
                    const int r = tbw * 4 + b;
                    float4 x = *(const float4*)(xb + r * 32 + ((kk ^ r) << 2));
                    unsigned long long dd0 = pack2(x.x, x.x);
                    ffma2(acc[b][0], dd0, w0.x); ffma2(acc[b][1], dd0, w0.y);
                    unsigned long long dd1 = pack2(x.y, x.y);
                    ffma2(acc[b][0], dd1, w1.x); ffma2(acc[b][1], dd1, w1.y);
                    unsigned long long dd2 = pack2(x.z, x.z);
                    ffma2(acc[b][0], dd2, w2.x); ffma2(acc[b][1], dd2, w2.y);
                    unsigned long long dd3 = pack2(x.w, x.w);
                    ffma2(acc[b][0], dd3, w3.x); ffma2(acc[b][1], dd3, w3.y);
                }
            }

            // stage chunk cch+2 into the buffer we just finished reading
            if (cch + 2 < NCHUNK) {
                const int k0n = (cch + 2) * KC;
                float* dst = ins + warpbase + (cch & 1) * BUFW;
                if (k0n < EMB) {
                    cp16_ca(dst + d0, esrc0 + k0n);
                    cp16_ca(dst + d1, esrc1 + k0n);
                } else {
                    const int ho = k0n - EMB + kc4;
                    cp16_cg(dst + d0, hread + hrow0 + ho);
                    cp16_cg(dst + d1, hread + hrow1 + ho);
                }
                asm volatile("cp.async.commit_group;");
            }
        }

        // pointwise LSTM cell
#pragma unroll
        for (int b = 0; b < 4; b++) {
            float2 g01 = unpack2(acc[b][0]);
            float2 g23 = unpack2(acc[b][1]);
            float ig = sigf(g01.x);
            float fg = sigf(g01.y);
            float gg = tanhx(g23.x);
            float og = sigf(g23.y);
            c[b] = fg * c[b] + ig * gg;
            float hv = og * tanhx(c[b]);
            hwrite[(size_t)(nb0 + tbw * 4 + b) * HID + jglob] = hv;
        }

        cur0 = nxt0;
        cur1 = nxt1;
        grid_sync();
    }

    // epilogue: h = h1*h2 -> FC(2) -> softmax
    if (bid == 0 && tid < NBATCH) {
        const int n = tid;
        const float* h1 = &g_h[0][(size_t)n * HID];
        const float* h2 = &g_h[0][(size_t)(n + NBATCH) * HID];
        float l0 = bfc[0], l1 = bfc[1];
#pragma unroll 4
        for (int j = 0; j < HID; j++) {
            float hp = __ldcg(&h1[j]) * __ldcg(&h2[j]);
            l0 = __fmaf_rn(hp, Wfc[j], l0);
            l1 = __fmaf_rn(hp, Wfc[HID + j], l1);
        }
        float m  = fmaxf(l0, l1);
        float e0 = __expf(l0 - m);
        float e1 = __expf(l1 - m);
        float s  = __fdividef(1.0f, e0 + e1);
        out[n * 2 + 0] = e0 * s;
        out[n * 2 + 1] = e1 * s;
    }
}

extern "C" void kernel_launch(void* const* d_in, const int* in_sizes, int n_in,
                              void* d_out, int out_size)
{
    (void)in_sizes; (void)n_in; (void)out_size;
    const int*   in1 = (const int*)d_in[0];
    const int*   in2 = (const int*)d_in[1];
    const float* emb = (const float*)d_in[2];
    const float* Wih = (const float*)d_in[3];
    const float* Whh = (const float*)d_in[4];
    const float* bih = (const float*)d_in[5];
    const float* bhh = (const float*)d_in[6];
    const float* Wfc = (const float*)d_in[7];
    const float* bfc = (const float*)d_in[8];
    float* out = (float*)d_out;

    cudaFuncSetAttribute(lstm_twin_kernel,
                         cudaFuncAttributeMaxDynamicSharedMemorySize, SMEM_BYTES);
    lstm_twin_kernel<<<NBLOCKS, THREADS, SMEM_BYTES>>>(
        in1, in2, emb, Wih, Whh, bih, bhh, Wfc, bfc, out);
}